// round 3
// baseline (speedup 1.0000x reference)
#include <cuda_runtime.h>
#include <math.h>

#define K        8
#define D        256
#define C4       (D / 4)     // 64 float4 columns
#define TILE_N   8           // rows per block (2 per thread along n)
#define THREADS  256
#define NEGV     (-1e9f)

// valid_mask may arrive as int32 / uint8(bool) / float32 depending on how the
// harness lowers jnp.bool_. Detect once from word 0 (guaranteed "true" since
// lengths >= N/2).
__device__ __forceinline__ bool mask_at(const void* m, int fmt, long i) {
    if (fmt == 1) return ((const unsigned char*)m)[i] != 0;
    if (fmt == 2) return ((const float*)m)[i] != 0.0f;
    return ((const int*)m)[i] != 0;
}

__global__ __launch_bounds__(THREADS)
void mixer_kernel(const float* __restrict__ x,
                  const float* __restrict__ dts,
                  const void*  __restrict__ maskp,
                  const float* __restrict__ w,
                  const float* __restrict__ beta,
                  float* __restrict__ out,
                  int N)
{
    __shared__ float s_alpha[TILE_N * K];

    const int  b    = blockIdx.y;
    const int  n0   = blockIdx.x * TILE_N;
    const int  tid  = threadIdx.x;
    const long base = (long)b * N;

    // ---- mask format detection (uniform across grid) ----
    const unsigned int w0 = *((const unsigned int*)maskp);
    int fmt = 0;
    if (w0 == 0x01010101u)      fmt = 1;   // uint8 bool
    else if (w0 == 0x3F800000u) fmt = 2;   // float32

    // ================= Phase 1: alpha[TILE_N][K] =================
    if (tid < TILE_N) {
        const int  n      = n0 + tid;
        const bool valid0 = mask_at(maskp, fmt, base + n);
        const float dt0   = dts[base + n];

        float score[K];
        bool  cv[K];
        cv[0]    = valid0;
        score[0] = valid0 ? 0.0f : NEGV;
        #pragma unroll
        for (int p = 1; p < K; p++) {
            const int np = n + p;
            bool  c  = false;
            float td = 0.0f;
            if (np < N) {
                c = valid0 && mask_at(maskp, fmt, base + np);
                if (c) td = fmaxf(dts[base + np] - dt0, 0.0f);
            }
            cv[p]    = c;
            score[p] = c ? -td : NEGV;
        }

        // temporal-decay softmax over offsets
        float m = score[0];
        #pragma unroll
        for (int p = 1; p < K; p++) m = fmaxf(m, score[p]);
        float e[K], es = 0.0f;
        #pragma unroll
        for (int p = 0; p < K; p++) { e[p] = __expf(score[p] - m); es += e[p]; }
        const float inv_es = 1.0f / es;

        // softmax(w) and sigmoid(beta)
        float wv[K];
        #pragma unroll
        for (int p = 0; p < K; p++) wv[p] = w[p];
        float wm = wv[0];
        #pragma unroll
        for (int p = 1; p < K; p++) wm = fmaxf(wm, wv[p]);
        float we[K], ws = 0.0f;
        #pragma unroll
        for (int p = 0; p < K; p++) { we[p] = __expf(wv[p] - wm); ws += we[p]; }
        const float inv_ws = 1.0f / ws;
        const float bsig   = 1.0f / (1.0f + __expf(-beta[0]));
        const float omb    = 1.0f - bsig;

        float a[K], asum = 0.0f;
        #pragma unroll
        for (int p = 0; p < K; p++) {
            a[p] = cv[p] ? (bsig * we[p] * inv_ws + omb * e[p] * inv_es) : 0.0f;
            asum += a[p];
        }
        const float inv = 1.0f / fmaxf(asum, 1e-8f);
        #pragma unroll
        for (int p = 0; p < K; p++) s_alpha[tid * K + p] = a[p] * inv;
    }
    __syncthreads();

    // ======= Phase 2: 2 output rows per thread, 9 loads front-batched =======
    const int c4 = tid & (C4 - 1);       // float4 column 0..63
    const int g  = tid >> 6;             // 0..3
    const int rl = g * 2;                // local rows rl, rl+1
    const int n  = n0 + rl;

    const float4* __restrict__ xr =
        (const float4*)x + (base + n) * (long)C4 + c4;
    float4* __restrict__ orow =
        (float4*)out + (base + n) * (long)C4 + c4;

    // 9 fully independent loads (MLP = 9)
    float4 v[K + 1];
    #pragma unroll
    for (int j = 0; j <= K; j++) {
        v[j] = (n + j < N) ? xr[(long)j * C4] : make_float4(0.f, 0.f, 0.f, 0.f);
    }

    // alphas for the two rows (LDS.128 broadcast within each 64-thread group)
    const float4* ar = (const float4*)&s_alpha[rl * K];
    const float4 a00 = ar[0], a01 = ar[1];   // row rl
    const float4 a10 = ar[2], a11 = ar[3];   // row rl+1
    const float al0[K] = {a00.x, a00.y, a00.z, a00.w, a01.x, a01.y, a01.z, a01.w};
    const float al1[K] = {a10.x, a10.y, a10.z, a10.w, a11.x, a11.y, a11.z, a11.w};

    float4 acc0 = make_float4(0.f, 0.f, 0.f, 0.f);
    float4 acc1 = make_float4(0.f, 0.f, 0.f, 0.f);
    #pragma unroll
    for (int p = 0; p < K; p++) {
        const float4 u0 = v[p];
        const float4 u1 = v[p + 1];
        acc0.x = fmaf(al0[p], u0.x, acc0.x);
        acc0.y = fmaf(al0[p], u0.y, acc0.y);
        acc0.z = fmaf(al0[p], u0.z, acc0.z);
        acc0.w = fmaf(al0[p], u0.w, acc0.w);
        acc1.x = fmaf(al1[p], u1.x, acc1.x);
        acc1.y = fmaf(al1[p], u1.y, acc1.y);
        acc1.z = fmaf(al1[p], u1.z, acc1.z);
        acc1.w = fmaf(al1[p], u1.w, acc1.w);
    }

    orow[0]  = acc0;
    orow[C4] = acc1;
}

extern "C" void kernel_launch(void* const* d_in, const int* in_sizes, int n_in,
                              void* d_out, int out_size)
{
    const float* x    = (const float*)d_in[0];
    const float* dts  = (const float*)d_in[1];
    const void*  mask = d_in[2];
    const float* w    = (const float*)d_in[3];
    const float* beta = (const float*)d_in[4];

    const int BN = in_sizes[1];   // B * N
    const int B  = 8;
    const int N  = BN / B;        // 4096

    dim3 grid(N / TILE_N, B);
    mixer_kernel<<<grid, THREADS>>>(x, dts, mask, w, beta, (float*)d_out, N);
}

// round 4
// speedup vs baseline: 1.5013x; 1.5013x over previous
#include <cuda_runtime.h>
#include <math.h>

#define K        8
#define C4       64          // 16-byte columns per row (d=256 floats)
#define TILE_N   64          // output rows per block
#define GROUPS   2
#define RPT      32          // rows per thread
#define THREADS  128         // 64 cols x 2 groups
#define WIN      16          // register ring depth (window 8 + prefetch 8)
#define NEGV     (-1e9f)

typedef unsigned long long u64;

// packed fp32x2 helpers (FFMA2 path, only reachable via PTX)
__device__ __forceinline__ u64 pack2(float a) {
    u64 d;
    asm("mov.b64 %0, {%1, %1};" : "=l"(d) : "f"(a));
    return d;
}
__device__ __forceinline__ void fma2(u64& acc, u64 v, u64 a) {
    asm("fma.rn.f32x2 %0, %1, %2, %3;" : "=l"(acc) : "l"(v), "l"(a), "l"(acc));
}

// valid_mask may arrive as int32 / uint8(bool) / float32; detect from word 0
// (guaranteed "true" since lengths >= N/2).
__device__ __forceinline__ bool mask_at(const void* m, int fmt, long i) {
    if (fmt == 1) return ((const unsigned char*)m)[i] != 0;
    if (fmt == 2) return ((const float*)m)[i] != 0.0f;
    return ((const int*)m)[i] != 0;
}

__global__ __launch_bounds__(THREADS, 4)
void mixer_kernel(const float* __restrict__ x,
                  const float* __restrict__ dts,
                  const void*  __restrict__ maskp,
                  const float* __restrict__ w,
                  const float* __restrict__ beta,
                  float* __restrict__ out,
                  int N)
{
    __shared__ float s_alpha[TILE_N * K];

    const int  b    = blockIdx.y;
    const int  n0   = blockIdx.x * TILE_N;
    const int  tid  = threadIdx.x;
    const long base = (long)b * N;

    // ---- per-thread column/row-strip mapping (phase 2) ----
    const int c4     = tid & (C4 - 1);   // 0..63
    const int g      = tid >> 6;         // 0..1
    const int r0     = g * RPT;
    const int nstart = n0 + r0;

    const ulonglong2* __restrict__ xr =
        (const ulonglong2*)x + (base + nstart) * (long)C4 + c4;
    ulonglong2* __restrict__ orow =
        (ulonglong2*)out + (base + nstart) * (long)C4 + c4;

    // ---- issue window-init loads FIRST (16 independent LDG.128) ----
    ulonglong2 buf[WIN];
    #pragma unroll
    for (int j = 0; j < WIN; j++) {
        const int nr = nstart + j;
        buf[j] = (nr < N) ? xr[(long)j * C4] : make_ulonglong2(0ULL, 0ULL);
    }

    // ---- mask format detection (uniform) ----
    const unsigned int w0 = *((const unsigned int*)maskp);
    int fmt = 0;
    if (w0 == 0x01010101u)      fmt = 1;   // uint8 bool
    else if (w0 == 0x3F800000u) fmt = 2;   // float32

    // ================= Phase 1: alpha[TILE_N][K] (overlaps window loads) ====
    if (tid < TILE_N) {
        const int  n      = n0 + tid;
        const bool valid0 = mask_at(maskp, fmt, base + n);
        const float dt0   = dts[base + n];

        float score[K];
        bool  cv[K];
        cv[0]    = valid0;
        score[0] = valid0 ? 0.0f : NEGV;
        #pragma unroll
        for (int p = 1; p < K; p++) {
            const int np = n + p;
            bool  c  = false;
            float td = 0.0f;
            if (np < N) {
                c = valid0 && mask_at(maskp, fmt, base + np);
                if (c) td = fmaxf(dts[base + np] - dt0, 0.0f);
            }
            cv[p]    = c;
            score[p] = c ? -td : NEGV;
        }

        float m = score[0];
        #pragma unroll
        for (int p = 1; p < K; p++) m = fmaxf(m, score[p]);
        float e[K], es = 0.0f;
        #pragma unroll
        for (int p = 0; p < K; p++) { e[p] = __expf(score[p] - m); es += e[p]; }
        const float inv_es = 1.0f / es;

        float wv[K];
        #pragma unroll
        for (int p = 0; p < K; p++) wv[p] = w[p];
        float wm = wv[0];
        #pragma unroll
        for (int p = 1; p < K; p++) wm = fmaxf(wm, wv[p]);
        float we[K], ws = 0.0f;
        #pragma unroll
        for (int p = 0; p < K; p++) { we[p] = __expf(wv[p] - wm); ws += we[p]; }
        const float inv_ws = 1.0f / ws;
        const float bsig   = 1.0f / (1.0f + __expf(-beta[0]));
        const float omb    = 1.0f - bsig;

        float a[K], asum = 0.0f;
        #pragma unroll
        for (int p = 0; p < K; p++) {
            a[p] = cv[p] ? (bsig * we[p] * inv_ws + omb * e[p] * inv_es) : 0.0f;
            asum += a[p];
        }
        const float inv = 1.0f / fmaxf(asum, 1e-8f);
        #pragma unroll
        for (int p = 0; p < K; p++) s_alpha[tid * K + p] = a[p] * inv;
    }
    __syncthreads();

    // ========== Phase 2: pipelined sliding window, 1 LDG per output ========
    #pragma unroll
    for (int r = 0; r < RPT; r++) {
        // alpha row (LDS.128 broadcast), packed for f32x2 FMA
        const float4* ar = (const float4*)&s_alpha[(r0 + r) * K];
        const float4 a0 = ar[0];
        const float4 a1 = ar[1];
        const u64 ap[K] = { pack2(a0.x), pack2(a0.y), pack2(a0.z), pack2(a0.w),
                            pack2(a1.x), pack2(a1.y), pack2(a1.z), pack2(a1.w) };

        u64 accx = 0ULL, accy = 0ULL;
        #pragma unroll
        for (int p = 0; p < K; p++) {
            const ulonglong2 v = buf[(r + p) & (WIN - 1)];
            fma2(accx, v.x, ap[p]);
            fma2(accy, v.y, ap[p]);
        }
        orow[(long)r * C4] = make_ulonglong2(accx, accy);

        // prefetch row r+WIN (consumed ~9 iterations later -> steady MLP ~ 8)
        if (r < RPT - 1) {
            const int nr = nstart + r + WIN;
            buf[r & (WIN - 1)] =
                (nr < N) ? xr[(long)(r + WIN) * C4] : make_ulonglong2(0ULL, 0ULL);
        }
    }
}

extern "C" void kernel_launch(void* const* d_in, const int* in_sizes, int n_in,
                              void* d_out, int out_size)
{
    const float* x    = (const float*)d_in[0];
    const float* dts  = (const float*)d_in[1];
    const void*  mask = d_in[2];
    const float* w    = (const float*)d_in[3];
    const float* beta = (const float*)d_in[4];

    const int BN = in_sizes[1];   // B * N
    const int B  = 8;
    const int N  = BN / B;        // 4096

    dim3 grid(N / TILE_N, B);
    mixer_kernel<<<grid, THREADS>>>(x, dts, mask, w, beta, (float*)d_out, N);
}